// round 1
// baseline (speedup 1.0000x reference)
#include <cuda_runtime.h>
#include <math.h>

#define BATCH 32
#define CIN   128
#define HH    64
#define WWD   64
#define HWN   4096
#define EB    128
#define EE    384

// ---------------- device scratch (no allocation allowed) ----------------
__device__ float g_fused[BATCH * EE * HWN];     // [b][c][hw]  201 MB
__device__ float g_wT3[9  * CIN * EB];          // [tap][ci][o]
__device__ float g_wT5[25 * CIN * EB];
__device__ float g_wT7[49 * CIN * EB];
__device__ float g_wfT[EE * EE];                // [c][o]
__device__ float g_avg[BATCH * EE];
__device__ float g_max[BATCH * EE];
__device__ float g_attn[BATCH * EE];

// ---------------- weight transpose: [O,I,kh,kw] -> [tap][ci][o] ---------
__device__ __forceinline__ void transpose_one(const float* __restrict__ w,
                                              float* __restrict__ wT,
                                              int idx, int taps, int ci_n, int co_n) {
    int o    = idx % co_n;
    int rest = idx / co_n;
    int ci   = rest % ci_n;
    int tap  = rest / ci_n;
    wT[idx] = w[(o * ci_n + ci) * taps + tap];
}

__global__ void prep_all(const float* __restrict__ w3, const float* __restrict__ w5,
                         const float* __restrict__ w7, const float* __restrict__ fw) {
    const int N3 = 9  * CIN * EB;
    const int N5 = 25 * CIN * EB;
    const int N7 = 49 * CIN * EB;
    const int NF = EE * EE;
    const int total = N3 + N5 + N7 + NF;
    for (int i = blockIdx.x * blockDim.x + threadIdx.x; i < total;
         i += gridDim.x * blockDim.x) {
        if (i < N3)                transpose_one(w3, g_wT3, i,            9,  CIN, EB);
        else if (i < N3 + N5)      transpose_one(w5, g_wT5, i - N3,       25, CIN, EB);
        else if (i < N3 + N5 + N7) transpose_one(w7, g_wT7, i - N3 - N5,  49, CIN, EB);
        else                       transpose_one(fw, g_wfT, i - N3 - N5 - N7, 1, EE, EE);
    }
}

// ---------------- implicit-GEMM conv ------------------------------------
// Block: 128 tokens (2 image rows) x 128 out channels. K chunks of 32.
// 256 threads, each owns an 8x8 micro-tile (8 tokens x 8 channels).
template<int KS>
__global__ __launch_bounds__(256) void conv_kernel(const float* __restrict__ x,
                                                   const float* __restrict__ bias,
                                                   int c0) {
    __shared__ __align__(16) float As[32][128];
    __shared__ __align__(16) float Bs[32][128];

    const float* wT = (KS == 3) ? g_wT3 : (KS == 5) ? g_wT5 : g_wT7;
    const int PAD = KS / 2;

    int tid     = threadIdx.x;
    int b       = blockIdx.y;
    int tileTok = blockIdx.x * 128;

    int txg = tid & 15;   // token group (8 tokens)
    int tyg = tid >> 4;   // channel group (8 channels)

    // loader mapping: fixed pixel per thread, ci strided by 2
    int pixL = tid & 127;
    int ciL0 = tid >> 7;   // 0 or 1
    int oL   = tid & 127;

    int token = tileTok + pixL;
    int py = token >> 6;
    int px = token & 63;

    const float* xb = x + (size_t)b * CIN * HWN;

    float acc[8][8];
    #pragma unroll
    for (int i = 0; i < 8; i++)
        #pragma unroll
        for (int j = 0; j < 8; j++) acc[i][j] = 0.f;

    for (int tap = 0; tap < KS * KS; ++tap) {
        int dy = tap / KS - PAD;
        int dx = tap % KS - PAD;
        int ys = py + dy;
        int xs = px + dx;
        bool valid = (ys >= 0) && (ys < HH) && (xs >= 0) && (xs < WWD);
        const float* xsrc = xb + ys * WWD + xs;

        for (int cic = 0; cic < CIN; cic += 32) {
            #pragma unroll
            for (int i = 0; i < 16; ++i) {
                int ci = ciL0 + 2 * i;
                As[ci][pixL] = valid ? xsrc[(cic + ci) * HWN] : 0.f;
            }
            const float* wsrc = wT + (tap * CIN + cic) * EB;
            #pragma unroll
            for (int i = 0; i < 16; ++i) {
                int ci = ciL0 + 2 * i;
                Bs[ci][oL] = wsrc[ci * EB + oL];
            }
            __syncthreads();
            #pragma unroll
            for (int ci = 0; ci < 32; ++ci) {
                float a[8], w8[8];
                *(float4*)&a[0]  = *(const float4*)&As[ci][txg * 8];
                *(float4*)&a[4]  = *(const float4*)&As[ci][txg * 8 + 4];
                *(float4*)&w8[0] = *(const float4*)&Bs[ci][tyg * 8];
                *(float4*)&w8[4] = *(const float4*)&Bs[ci][tyg * 8 + 4];
                #pragma unroll
                for (int i = 0; i < 8; i++)
                    #pragma unroll
                    for (int j = 0; j < 8; j++)
                        acc[i][j] += a[i] * w8[j];
            }
            __syncthreads();
        }
    }

    // epilogue: g_fused[b][c0+ch][token], contiguous in token
    #pragma unroll
    for (int j = 0; j < 8; j++) {
        int chL = tyg * 8 + j;
        float bv = bias[chL];
        float* dst = g_fused + ((size_t)b * EE + c0 + chL) * HWN + tileTok + txg * 8;
        float4 v0 = make_float4(acc[0][j] + bv, acc[1][j] + bv, acc[2][j] + bv, acc[3][j] + bv);
        float4 v1 = make_float4(acc[4][j] + bv, acc[5][j] + bv, acc[6][j] + bv, acc[7][j] + bv);
        *(float4*)&dst[0] = v0;
        *(float4*)&dst[4] = v1;
    }
}

// ---------------- global avg & max pool over HW --------------------------
__global__ void pool_kernel() {
    int row = blockIdx.x;                 // b*EE + c
    const float* p = g_fused + (size_t)row * HWN;
    int tid = threadIdx.x;
    float s = 0.f, m = -INFINITY;
    for (int i = tid; i < HWN; i += 256) {
        float v = p[i];
        s += v;
        m = fmaxf(m, v);
    }
    __shared__ float ss[256], sm[256];
    ss[tid] = s; sm[tid] = m;
    __syncthreads();
    for (int st = 128; st > 0; st >>= 1) {
        if (tid < st) {
            ss[tid] += ss[tid + st];
            sm[tid]  = fmaxf(sm[tid], sm[tid + st]);
        }
        __syncthreads();
    }
    if (tid == 0) {
        g_avg[row] = ss[0] * (1.f / HWN);
        g_max[row] = sm[0];
    }
}

// ---------------- channel-attention MLP ----------------------------------
__global__ void attn_kernel(const float* __restrict__ cw1, const float* __restrict__ cw2) {
    __shared__ float h1[24], h2[24];
    int b = blockIdx.x;
    int tid = threadIdx.x;  // 384 threads
    if (tid < 24) {
        float s = 0.f;
        const float* w = cw1 + tid * EE;
        const float* v = g_avg + b * EE;
        #pragma unroll 4
        for (int c = 0; c < EE; ++c) s += v[c] * w[c];
        h1[tid] = fmaxf(s, 0.f);
    } else if (tid < 48) {
        int j = tid - 24;
        float s = 0.f;
        const float* w = cw1 + j * EE;
        const float* v = g_max + b * EE;
        #pragma unroll 4
        for (int c = 0; c < EE; ++c) s += v[c] * w[c];
        h2[j] = fmaxf(s, 0.f);
    }
    __syncthreads();
    float s = 0.f;
    const float* w = cw2 + tid * 24;
    #pragma unroll
    for (int j = 0; j < 24; ++j) s += (h1[j] + h2[j]) * w[j];
    g_attn[b * EE + tid] = 1.f / (1.f + expf(-s));
}

// ---------------- 1x1 fusion GEMM with attention gate --------------------
// Block: 128 tokens x 128 out channels; grid.z covers 3 N-tiles of 384.
__global__ __launch_bounds__(256) void fuse_gemm_kernel(const float* __restrict__ fb,
                                                        float* __restrict__ out) {
    __shared__ __align__(16) float As[32][128];
    __shared__ __align__(16) float Bs[32][128];
    __shared__ float s_attn[EE];

    int tid     = threadIdx.x;
    int b       = blockIdx.y;
    int tileTok = blockIdx.x * 128;
    int nb      = blockIdx.z * 128;

    for (int i = tid; i < EE; i += 256) s_attn[i] = g_attn[b * EE + i];
    __syncthreads();

    int txg = tid & 15, tyg = tid >> 4;
    int pixL = tid & 127, ciL0 = tid >> 7, oL = tid & 127;

    float acc[8][8];
    #pragma unroll
    for (int i = 0; i < 8; i++)
        #pragma unroll
        for (int j = 0; j < 8; j++) acc[i][j] = 0.f;

    const float* ab = g_fused + (size_t)b * EE * HWN + tileTok + pixL;

    for (int cic = 0; cic < EE; cic += 32) {
        #pragma unroll
        for (int i = 0; i < 16; ++i) {
            int ci = ciL0 + 2 * i;
            As[ci][pixL] = ab[(size_t)(cic + ci) * HWN] * s_attn[cic + ci];
        }
        const float* wsrc = g_wfT + (size_t)cic * EE + nb;
        #pragma unroll
        for (int i = 0; i < 16; ++i) {
            int ci = ciL0 + 2 * i;
            Bs[ci][oL] = wsrc[ci * EE + oL];
        }
        __syncthreads();
        #pragma unroll
        for (int ci = 0; ci < 32; ++ci) {
            float a[8], w8[8];
            *(float4*)&a[0]  = *(const float4*)&As[ci][txg * 8];
            *(float4*)&a[4]  = *(const float4*)&As[ci][txg * 8 + 4];
            *(float4*)&w8[0] = *(const float4*)&Bs[ci][tyg * 8];
            *(float4*)&w8[4] = *(const float4*)&Bs[ci][tyg * 8 + 4];
            #pragma unroll
            for (int i = 0; i < 8; i++)
                #pragma unroll
                for (int j = 0; j < 8; j++)
                    acc[i][j] += a[i] * w8[j];
        }
        __syncthreads();
    }

    // epilogue: out[b][token][e], e contiguous per token
    #pragma unroll
    for (int i = 0; i < 8; i++) {
        int token = tileTok + txg * 8 + i;
        float* dst = out + ((size_t)b * HWN + token) * EE + nb + tyg * 8;
        float b0 = fb[nb + tyg * 8 + 0], b1 = fb[nb + tyg * 8 + 1];
        float b2 = fb[nb + tyg * 8 + 2], b3 = fb[nb + tyg * 8 + 3];
        float b4 = fb[nb + tyg * 8 + 4], b5 = fb[nb + tyg * 8 + 5];
        float b6 = fb[nb + tyg * 8 + 6], b7 = fb[nb + tyg * 8 + 7];
        float4 v0 = make_float4(acc[i][0] + b0, acc[i][1] + b1, acc[i][2] + b2, acc[i][3] + b3);
        float4 v1 = make_float4(acc[i][4] + b4, acc[i][5] + b5, acc[i][6] + b6, acc[i][7] + b7);
        *(float4*)&dst[0] = v0;
        *(float4*)&dst[4] = v1;
    }
}

// ---------------- LayerNorm over E (in-place on d_out) -------------------
__global__ void ln_kernel(float* __restrict__ out, const float* __restrict__ g,
                          const float* __restrict__ beta) {
    int tokrow = blockIdx.x;                       // b*HWN + token
    float* p = out + (size_t)tokrow * EE;
    int tid = threadIdx.x;                          // 128 threads
    float v0 = p[tid], v1 = p[tid + 128], v2 = p[tid + 256];
    float s = v0 + v1 + v2;
    float q = v0 * v0 + v1 * v1 + v2 * v2;
    // warp reduce then cross-warp
    #pragma unroll
    for (int off = 16; off > 0; off >>= 1) {
        s += __shfl_down_sync(0xffffffffu, s, off);
        q += __shfl_down_sync(0xffffffffu, q, off);
    }
    __shared__ float rs[4], rq[4];
    __shared__ float smean, srstd;
    int wid = tid >> 5, lane = tid & 31;
    if (lane == 0) { rs[wid] = s; rq[wid] = q; }
    __syncthreads();
    if (tid == 0) {
        float ts = rs[0] + rs[1] + rs[2] + rs[3];
        float tq = rq[0] + rq[1] + rq[2] + rq[3];
        float mean = ts * (1.f / EE);
        float var  = tq * (1.f / EE) - mean * mean;
        smean = mean;
        srstd = rsqrtf(var + 1e-5f);
    }
    __syncthreads();
    float mean = smean, rstd = srstd;
    p[tid]       = (v0 - mean) * rstd * g[tid]       + beta[tid];
    p[tid + 128] = (v1 - mean) * rstd * g[tid + 128] + beta[tid + 128];
    p[tid + 256] = (v2 - mean) * rstd * g[tid + 256] + beta[tid + 256];
}

// ---------------- launch ---------------------------------------------------
extern "C" void kernel_launch(void* const* d_in, const int* in_sizes, int n_in,
                              void* d_out, int out_size) {
    const float* x   = (const float*)d_in[0];
    const float* w3  = (const float*)d_in[1];
    const float* b3  = (const float*)d_in[2];
    const float* w5  = (const float*)d_in[3];
    const float* b5  = (const float*)d_in[4];
    const float* w7  = (const float*)d_in[5];
    const float* b7  = (const float*)d_in[6];
    const float* cw1 = (const float*)d_in[7];
    const float* cw2 = (const float*)d_in[8];
    const float* fw  = (const float*)d_in[9];
    const float* fb  = (const float*)d_in[10];
    const float* lng = (const float*)d_in[11];
    const float* lnb = (const float*)d_in[12];
    float* out = (float*)d_out;

    prep_all<<<2944, 256>>>(w3, w5, w7, fw);

    dim3 cgrid(HWN / 128, BATCH);
    conv_kernel<3><<<cgrid, 256>>>(x, b3, 0);
    conv_kernel<5><<<cgrid, 256>>>(x, b5, EB);
    conv_kernel<7><<<cgrid, 256>>>(x, b7, 2 * EB);

    pool_kernel<<<BATCH * EE, 256>>>();
    attn_kernel<<<BATCH, EE>>>(cw1, cw2);

    dim3 ggrid(HWN / 128, BATCH, 3);
    fuse_gemm_kernel<<<ggrid, 256>>>(fb, out);

    ln_kernel<<<BATCH * HWN, 128>>>(out, lng, lnb);
}

// round 7
// speedup vs baseline: 1.5384x; 1.5384x over previous
#include <cuda_runtime.h>
#include <cuda_bf16.h>
#include <cstdint>
#include <math.h>

#define BATCH 32
#define CIN   128
#define HWN   4096
#define EB    128
#define EE    384
#define PADK  40   // padded K-row length (u16 elems) -> 80B rows, ldmatrix conflict-free

// ---------------- device scratch (no allocation allowed) ----------------
__device__ float    g_fused[(size_t)BATCH * EE * HWN];   // [b][c][hw]
__device__ uint32_t g_xp[(size_t)BATCH * CIN * HWN];     // packed (hi | lo<<16) bf16 of x
__device__ uint16_t g_w3h[9  * 128 * 128], g_w3l[9  * 128 * 128];  // [tap][o][ci]
__device__ uint16_t g_w5h[25 * 128 * 128], g_w5l[25 * 128 * 128];
__device__ uint16_t g_w7h[49 * 128 * 128], g_w7l[49 * 128 * 128];
__device__ uint16_t g_wfh[EE * EE],        g_wfl[EE * EE];         // [o][c]
__device__ float    g_avg[BATCH * EE];
__device__ float    g_max[BATCH * EE];
__device__ float    g_attn[BATCH * EE];

// ---------------- helpers -------------------------------------------------
__device__ __forceinline__ uint32_t smem_u32(const void* p) {
    uint32_t a;
    asm("{ .reg .u64 t; cvta.to.shared.u64 t, %1; cvt.u32.u64 %0, t; }" : "=r"(a) : "l"(p));
    return a;
}

#define LDSM_X4(r0, r1, r2, r3, addr) \
    asm volatile("ldmatrix.sync.aligned.m8n8.x4.shared.b16 {%0,%1,%2,%3}, [%4];" \
                 : "=r"(r0), "=r"(r1), "=r"(r2), "=r"(r3) : "r"(addr))

__device__ __forceinline__ void mma_bf16(float* c, const uint32_t* a,
                                         uint32_t b0, uint32_t b1) {
    asm volatile(
        "mma.sync.aligned.m16n8k16.row.col.f32.bf16.bf16.f32 "
        "{%0,%1,%2,%3}, {%4,%5,%6,%7}, {%8,%9}, {%0,%1,%2,%3};"
        : "+f"(c[0]), "+f"(c[1]), "+f"(c[2]), "+f"(c[3])
        : "r"(a[0]), "r"(a[1]), "r"(a[2]), "r"(a[3]), "r"(b0), "r"(b1));
}

__device__ __forceinline__ void bf_split(float v, uint16_t& h, uint16_t& l) {
    __nv_bfloat16 bh = __float2bfloat16(v);
    float rem = v - __bfloat162float(bh);
    __nv_bfloat16 bl = __float2bfloat16(rem);
    h = *reinterpret_cast<uint16_t*>(&bh);
    l = *reinterpret_cast<uint16_t*>(&bl);
}

// ---------------- prep kernels --------------------------------------------
__global__ void prep_x(const float* __restrict__ x) {
    size_t i = (size_t)blockIdx.x * blockDim.x + threadIdx.x;
    if (i >= (size_t)BATCH * CIN * HWN) return;
    uint16_t h, l;
    bf_split(x[i], h, l);
    g_xp[i] = (uint32_t)h | ((uint32_t)l << 16);
}

template<int TAPS>
__global__ void prep_wc(const float* __restrict__ w) {
    uint16_t* wh = (TAPS == 3) ? g_w3h : (TAPS == 5) ? g_w5h : g_w7h;
    uint16_t* wl = (TAPS == 3) ? g_w3l : (TAPS == 5) ? g_w5l : g_w7l;
    int idx = blockIdx.x * blockDim.x + threadIdx.x;
    if (idx >= TAPS * TAPS * 128 * 128) return;
    int tap  = idx >> 14;
    int rest = idx & 16383;
    int o    = rest >> 7;
    int ci   = rest & 127;
    float v = w[(o * CIN + ci) * (TAPS * TAPS) + tap];
    uint16_t h, l; bf_split(v, h, l);
    wh[idx] = h;
    wl[idx] = l;
}

__global__ void prep_wf(const float* __restrict__ fw) {
    int idx = blockIdx.x * blockDim.x + threadIdx.x;
    if (idx >= EE * EE) return;
    uint16_t h, l; bf_split(fw[idx], h, l);
    g_wfh[idx] = h;
    g_wfl[idx] = l;
}

// ---------------- tensor-core matmul kernel (mma.sync bf16, 3-term split) --
// TAPS in {3,5,7}: conv branch writing g_fused at channel offset c0.
// TAPS==0: 1x1 fusion GEMM with attention gate; writes out[b][tok][e].
// CTA: 128 tokens x 128 out-channels. 8 warps (4 M x 2 N), warp tile 32x64.
template<int TAPS>
__global__ __launch_bounds__(256, 2) void mm_kernel(const float* __restrict__ bias,
                                                    float* __restrict__ out, int c0) {
    __shared__ __align__(16) uint16_t Ah[128 * PADK], Al[128 * PADK];
    __shared__ __align__(16) uint16_t Wh[128 * PADK], Wl[128 * PADK];
    __shared__ float s_attn[EE];

    const int tid = threadIdx.x;
    const int b   = blockIdx.y;
    const int tileTok = blockIdx.x * 128;
    const int nb = (TAPS == 0) ? blockIdx.z : 0;

    if (TAPS == 0)
        for (int i = tid; i < EE; i += 256) s_attn[i] = g_attn[b * EE + i];

    const int lane = tid & 31, wid = tid >> 5;
    const int wm = wid & 3, wn = wid >> 2;
    const int tokL = tid & 127, half = tid >> 7, oL = tid & 127;
    const int token = tileTok + tokL;
    const int py = token >> 6, px = token & 63;

    float acc[2][8][4];
    #pragma unroll
    for (int mi = 0; mi < 2; ++mi)
        #pragma unroll
        for (int ni = 0; ni < 8; ++ni)
            #pragma unroll
            for (int q = 0; q < 4; ++q) acc[mi][ni][q] = 0.f;

    const uint32_t sAh = smem_u32(Ah), sAl = smem_u32(Al);
    const uint32_t sWh = smem_u32(Wh), sWl = smem_u32(Wl);

    const int NT = (TAPS == 0) ? 1 : TAPS * TAPS;
    const int NC = (TAPS == 0) ? 12 : 4;    // 32-wide K chunks per tap
    const uint16_t* gwh = (TAPS == 3) ? g_w3h : (TAPS == 5) ? g_w5h
                         : (TAPS == 7) ? g_w7h : g_wfh;
    const uint16_t* gwl = (TAPS == 3) ? g_w3l : (TAPS == 5) ? g_w5l
                         : (TAPS == 7) ? g_w7l : g_wfl;

    // ldmatrix lane->address maps (byte offsets)
    // A (row-major, x4): lanes 0-15 -> rows 0-15 @k0, lanes 16-31 -> rows 0-15 @k8
    const uint32_t aoff0 = ((uint32_t)((wm * 32 + (lane & 15)) * PADK + ((lane >> 4) << 3))) * 2;
    // W ([n][k] = col-major B, x4 non-trans):
    // lanes 0-7 -> n0-7@k0 (b0,g0), 8-15 -> n0-7@k8 (b1,g0), 16-23 -> n8-15@k0, 24-31 -> n8-15@k8
    const uint32_t woffb = ((uint32_t)((wn * 64 + (lane & 7) + ((lane >> 4) << 3)) * PADK
                                      + (((lane >> 3) & 1) << 3))) * 2;

    for (int tap = 0; tap < NT; ++tap) {
        const uint32_t* asrc = nullptr;
        bool valid = true;
        if (TAPS > 0) {
            int dy = tap / TAPS - TAPS / 2, dx = tap % TAPS - TAPS / 2;
            int ys = py + dy, xs = px + dx;
            valid = ((unsigned)ys < 64u) && ((unsigned)xs < 64u);
            asrc = g_xp + (size_t)b * CIN * HWN + ys * 64 + xs;
        }
        for (int cc = 0; cc < NC; ++cc) {
            const int cic = cc * 32;
            __syncthreads();   // all warps done reading previous chunk

            // ---- stage A (128 tok x 32 k), hi/lo u16 ----
            if (TAPS > 0) {
                #pragma unroll
                for (int i = 0; i < 16; ++i) {
                    int cl = half * 16 + i;
                    uint32_t u = valid ? __ldg(asrc + (size_t)(cic + cl) * HWN) : 0u;
                    Ah[tokL * PADK + cl] = (uint16_t)u;
                    Al[tokL * PADK + cl] = (uint16_t)(u >> 16);
                }
            } else {
                const float* fsrc = g_fused + (size_t)b * EE * HWN + tileTok + tokL;
                #pragma unroll
                for (int i = 0; i < 16; ++i) {
                    int cl = half * 16 + i;
                    float v = __ldg(fsrc + (size_t)(cic + cl) * HWN) * s_attn[cic + cl];
                    uint16_t h, l; bf_split(v, h, l);
                    Ah[tokL * PADK + cl] = h;
                    Al[tokL * PADK + cl] = l;
                }
            }

            // ---- stage W (128 o x 32 k), vectorized, conflict-free ----
            {
                size_t rowoff = (TAPS == 0)
                    ? ((size_t)(nb * 128 + oL) * EE + cic)
                    : ((size_t)(tap * 128 + oL) * 128 + cic);
                const uint4* sh = (const uint4*)(gwh + rowoff);
                const uint4* sl = (const uint4*)(gwl + rowoff);
                #pragma unroll
                for (int j = 0; j < 2; ++j) {
                    uint4 vh = sh[half * 2 + j];
                    uint4 vl = sl[half * 2 + j];
                    *(uint4*)&Wh[oL * PADK + half * 16 + j * 8] = vh;
                    *(uint4*)&Wl[oL * PADK + half * 16 + j * 8] = vl;
                }
            }
            __syncthreads();

            // ---- compute: 2 k16-steps, 3-term bf16 split ----
            #pragma unroll
            for (int k16 = 0; k16 < 2; ++k16) {
                const uint32_t kb = (uint32_t)(k16 * 16) * 2;
                uint32_t ahf[2][4], alf[2][4];
                #pragma unroll
                for (int mi = 0; mi < 2; ++mi) {
                    uint32_t ao = aoff0 + (uint32_t)(mi * 16 * PADK) * 2 + kb;
                    LDSM_X4(ahf[mi][0], ahf[mi][1], ahf[mi][2], ahf[mi][3], sAh + ao);
                    LDSM_X4(alf[mi][0], alf[mi][1], alf[mi][2], alf[mi][3], sAl + ao);
                }
                #pragma unroll
                for (int nh = 0; nh < 4; ++nh) {
                    uint32_t wo = woffb + (uint32_t)(nh * 16 * PADK) * 2 + kb;
                    uint32_t whf[4], wlf[4];
                    LDSM_X4(whf[0], whf[1], whf[2], whf[3], sWh + wo);
                    LDSM_X4(wlf[0], wlf[1], wlf[2], wlf[3], sWl + wo);
                    #pragma unroll
                    for (int mi = 0; mi < 2; ++mi) {
                        mma_bf16(acc[mi][nh * 2],     ahf[mi], whf[0], whf[1]);
                        mma_bf16(acc[mi][nh * 2 + 1], ahf[mi], whf[2], whf[3]);
                        mma_bf16(acc[mi][nh * 2],     alf[mi], whf[0], whf[1]);
                        mma_bf16(acc[mi][nh * 2 + 1], alf[mi], whf[2], whf[3]);
                        mma_bf16(acc[mi][nh * 2],     ahf[mi], wlf[0], wlf[1]);
                        mma_bf16(acc[mi][nh * 2 + 1], ahf[mi], wlf[2], wlf[3]);
                    }
                }
            }
        }
    }

    // ---- epilogue ----
    const int r0 = wm * 32 + (lane >> 2);
    if (TAPS > 0) {
        #pragma unroll
        for (int ni = 0; ni < 8; ++ni) {
            int ch = wn * 64 + ni * 8 + (lane & 3) * 2;
            float bv0 = __ldg(bias + ch), bv1 = __ldg(bias + ch + 1);
            float* d0 = g_fused + ((size_t)b * EE + c0 + ch) * HWN + tileTok;
            float* d1 = d0 + HWN;
            #pragma unroll
            for (int mi = 0; mi < 2; ++mi) {
                int m = r0 + mi * 16;
                d0[m]     = acc[mi][ni][0] + bv0;
                d1[m]     = acc[mi][ni][1] + bv1;
                d0[m + 8] = acc[mi][ni][2] + bv0;
                d1[m + 8] = acc[mi][ni][3] + bv1;
            }
        }
    } else {
        #pragma unroll
        for (int ni = 0; ni < 8; ++ni) {
            int chl = wn * 64 + ni * 8 + (lane & 3) * 2;
            int e = nb * 128 + chl;
            float bv0 = __ldg(bias + e), bv1 = __ldg(bias + e + 1);
            #pragma unroll
            for (int mi = 0; mi < 2; ++mi) {
                int m = r0 + mi * 16;
                float* da = out + ((size_t)b * HWN + tileTok + m) * EE + e;
                float* db = out + ((size_t)b * HWN + tileTok + m + 8) * EE + e;
                float2 va = make_float2(acc[mi][ni][0] + bv0, acc[mi][ni][1] + bv1);
                float2 vb = make_float2(acc[mi][ni][2] + bv0, acc[mi][ni][3] + bv1);
                *(float2*)da = va;
                *(float2*)db = vb;
            }
        }
    }
}

// ---------------- pool / attention / layernorm (unchanged, passing) ------
__global__ void pool_kernel() {
    int row = blockIdx.x;
    const float* p = g_fused + (size_t)row * HWN;
    int tid = threadIdx.x;
    float s = 0.f, m = -INFINITY;
    for (int i = tid; i < HWN; i += 256) { float v = p[i]; s += v; m = fmaxf(m, v); }
    __shared__ float ss[256], sm[256];
    ss[tid] = s; sm[tid] = m;
    __syncthreads();
    for (int st = 128; st > 0; st >>= 1) {
        if (tid < st) { ss[tid] += ss[tid + st]; sm[tid] = fmaxf(sm[tid], sm[tid + st]); }
        __syncthreads();
    }
    if (tid == 0) { g_avg[row] = ss[0] * (1.f / HWN); g_max[row] = sm[0]; }
}

__global__ void attn_kernel(const float* __restrict__ cw1, const float* __restrict__ cw2) {
    __shared__ float h1[24], h2[24];
    int b = blockIdx.x;
    int tid = threadIdx.x;
    if (tid < 24) {
        float s = 0.f;
        const float* w = cw1 + tid * EE;
        const float* v = g_avg + b * EE;
        #pragma unroll 4
        for (int c = 0; c < EE; ++c) s += v[c] * w[c];
        h1[tid] = fmaxf(s, 0.f);
    } else if (tid < 48) {
        int j = tid - 24;
        float s = 0.f;
        const float* w = cw1 + j * EE;
        const float* v = g_max + b * EE;
        #pragma unroll 4
        for (int c = 0; c < EE; ++c) s += v[c] * w[c];
        h2[j] = fmaxf(s, 0.f);
    }
    __syncthreads();
    float s = 0.f;
    const float* w = cw2 + tid * 24;
    #pragma unroll
    for (int j = 0; j < 24; ++j) s += (h1[j] + h2[j]) * w[j];
    g_attn[b * EE + tid] = 1.f / (1.f + expf(-s));
}

__global__ void ln_kernel(float* __restrict__ out, const float* __restrict__ g,
                          const float* __restrict__ beta) {
    int tokrow = blockIdx.x;
    float* p = out + (size_t)tokrow * EE;
    int tid = threadIdx.x;
    float v0 = p[tid], v1 = p[tid + 128], v2 = p[tid + 256];
    float s = v0 + v1 + v2;
    float q = v0 * v0 + v1 * v1 + v2 * v2;
    #pragma unroll
    for (int off = 16; off > 0; off >>= 1) {
        s += __shfl_down_sync(0xffffffffu, s, off);
        q += __shfl_down_sync(0xffffffffu, q, off);
    }
    __shared__ float rs[4], rq[4];
    __shared__ float smean, srstd;
    int wid = tid >> 5, lane = tid & 31;
    if (lane == 0) { rs[wid] = s; rq[wid] = q; }
    __syncthreads();
    if (tid == 0) {
        float ts = rs[0] + rs[1] + rs[2] + rs[3];
        float tq = rq[0] + rq[1] + rq[2] + rq[3];
        float mean = ts * (1.f / EE);
        float var  = tq * (1.f / EE) - mean * mean;
        smean = mean;
        srstd = rsqrtf(var + 1e-5f);
    }
    __syncthreads();
    float mean = smean, rstd = srstd;
    p[tid]       = (v0 - mean) * rstd * g[tid]       + beta[tid];
    p[tid + 128] = (v1 - mean) * rstd * g[tid + 128] + beta[tid + 128];
    p[tid + 256] = (v2 - mean) * rstd * g[tid + 256] + beta[tid + 256];
}

// ---------------- launch ---------------------------------------------------
extern "C" void kernel_launch(void* const* d_in, const int* in_sizes, int n_in,
                              void* d_out, int out_size) {
    const float* x   = (const float*)d_in[0];
    const float* w3  = (const float*)d_in[1];
    const float* b3  = (const float*)d_in[2];
    const float* w5  = (const float*)d_in[3];
    const float* b5  = (const float*)d_in[4];
    const float* w7  = (const float*)d_in[5];
    const float* b7  = (const float*)d_in[6];
    const float* cw1 = (const float*)d_in[7];
    const float* cw2 = (const float*)d_in[8];
    const float* fw  = (const float*)d_in[9];
    const float* fb  = (const float*)d_in[10];
    const float* lng = (const float*)d_in[11];
    const float* lnb = (const float*)d_in[12];
    float* out = (float*)d_out;

    prep_x<<<(BATCH * CIN * HWN + 255) / 256, 256>>>(x);
    prep_wc<3><<<(9  * 16384 + 255) / 256, 256>>>(w3);
    prep_wc<5><<<(25 * 16384 + 255) / 256, 256>>>(w5);
    prep_wc<7><<<(49 * 16384 + 255) / 256, 256>>>(w7);
    prep_wf<<<(EE * EE + 255) / 256, 256>>>(fw);

    dim3 cgrid(HWN / 128, BATCH);
    mm_kernel<3><<<cgrid, 256>>>(b3, nullptr, 0);
    mm_kernel<5><<<cgrid, 256>>>(b5, nullptr, EB);
    mm_kernel<7><<<cgrid, 256>>>(b7, nullptr, 2 * EB);

    pool_kernel<<<BATCH * EE, 256>>>();
    attn_kernel<<<BATCH, EE>>>(cw1, cw2);

    dim3 ggrid(HWN / 128, BATCH, 3);
    mm_kernel<0><<<ggrid, 256>>>(fb, out, 0);

    ln_kernel<<<BATCH * HWN, 128>>>(out, lng, lnb);
}

// round 9
// speedup vs baseline: 1.9849x; 1.2903x over previous
#include <cuda_runtime.h>
#include <cuda_bf16.h>
#include <cstdint>
#include <math.h>

#define BATCH 32
#define CIN   128
#define HWN   4096
#define EB    128
#define EE    384
#define GUARD 512
#define NX    ((size_t)BATCH * CIN * HWN)

// SMEM layout (bytes): A rows=[k][tok] 272B, W rows=[n][k] 144B
#define AROW  272
#define WROW  144
#define OFF_AH   0
#define OFF_AL   17408
#define OFF_WH   34816
#define OFF_WL   53248
#define OFF_ATTN 71680
#define SMEM_SZ  73728

// ---------------- device scratch (no allocation allowed) ----------------
__device__ float    g_fused[(size_t)BATCH * EE * HWN];          // [b][c][hw]
__device__ __align__(16) uint16_t g_xh0[NX + 2 * GUARD];        // hi plane
__device__ __align__(16) uint16_t g_xl0[NX + 2 * GUARD];        // lo plane
__device__ __align__(16) uint16_t g_xh1[NX + 2 * GUARD];        // hi, shifted by 1 tok
__device__ __align__(16) uint16_t g_xl1[NX + 2 * GUARD];        // lo, shifted
__device__ uint16_t g_w3h[9  * 128 * 128], g_w3l[9  * 128 * 128];  // [tap][o][ci]
__device__ uint16_t g_w5h[25 * 128 * 128], g_w5l[25 * 128 * 128];
__device__ uint16_t g_w7h[49 * 128 * 128], g_w7l[49 * 128 * 128];
__device__ uint16_t g_wfh[EE * EE],        g_wfl[EE * EE];         // [o][c]
__device__ float    g_avg[BATCH * EE];
__device__ float    g_max[BATCH * EE];
__device__ float    g_attn[BATCH * EE];

// ---------------- helpers -------------------------------------------------
__device__ __forceinline__ uint32_t smem_u32(const void* p) {
    uint32_t a;
    asm("{ .reg .u64 t; cvta.to.shared.u64 t, %1; cvt.u32.u64 %0, t; }" : "=r"(a) : "l"(p));
    return a;
}

#define LDSM_X4(r0, r1, r2, r3, addr) \
    asm volatile("ldmatrix.sync.aligned.m8n8.x4.shared.b16 {%0,%1,%2,%3}, [%4];" \
                 : "=r"(r0), "=r"(r1), "=r"(r2), "=r"(r3) : "r"(addr))

#define LDSM_X4T(r0, r1, r2, r3, addr) \
    asm volatile("ldmatrix.sync.aligned.m8n8.x4.trans.shared.b16 {%0,%1,%2,%3}, [%4];" \
                 : "=r"(r0), "=r"(r1), "=r"(r2), "=r"(r3) : "r"(addr))

__device__ __forceinline__ void mma_bf16(float* c, const uint32_t* a,
                                         uint32_t b0, uint32_t b1) {
    asm volatile(
        "mma.sync.aligned.m16n8k16.row.col.f32.bf16.bf16.f32 "
        "{%0,%1,%2,%3}, {%4,%5,%6,%7}, {%8,%9}, {%0,%1,%2,%3};"
        : "+f"(c[0]), "+f"(c[1]), "+f"(c[2]), "+f"(c[3])
        : "r"(a[0]), "r"(a[1]), "r"(a[2]), "r"(a[3]), "r"(b0), "r"(b1));
}

__device__ __forceinline__ void bf_split(float v, uint16_t& h, uint16_t& l) {
    __nv_bfloat16 bh = __float2bfloat16(v);
    float rem = v - __bfloat162float(bh);
    __nv_bfloat16 bl = __float2bfloat16(rem);
    h = *reinterpret_cast<uint16_t*>(&bh);
    l = *reinterpret_cast<uint16_t*>(&bl);
}

// ---------------- prep kernels --------------------------------------------
__global__ void prep_x(const float* __restrict__ x) {
    size_t i = (size_t)blockIdx.x * blockDim.x + threadIdx.x;
    if (i >= NX) return;
    uint16_t h, l;
    bf_split(x[i], h, l);
    g_xh0[GUARD + i] = h;
    g_xl0[GUARD + i] = l;
    g_xh1[GUARD + i - 1] = h;   // plane1[j] = x[j+1]
    g_xl1[GUARD + i - 1] = l;
}

template<int TAPS>
__global__ void prep_wc(const float* __restrict__ w) {
    uint16_t* wh = (TAPS == 3) ? g_w3h : (TAPS == 5) ? g_w5h : g_w7h;
    uint16_t* wl = (TAPS == 3) ? g_w3l : (TAPS == 5) ? g_w5l : g_w7l;
    int idx = blockIdx.x * blockDim.x + threadIdx.x;
    if (idx >= TAPS * TAPS * 128 * 128) return;
    int tap  = idx >> 14;
    int rest = idx & 16383;
    int o    = rest >> 7;
    int ci   = rest & 127;
    float v = w[(o * CIN + ci) * (TAPS * TAPS) + tap];
    uint16_t h, l; bf_split(v, h, l);
    wh[idx] = h;
    wl[idx] = l;
}

__global__ void prep_wf(const float* __restrict__ fw) {
    int idx = blockIdx.x * blockDim.x + threadIdx.x;
    if (idx >= EE * EE) return;
    uint16_t h, l; bf_split(fw[idx], h, l);
    g_wfh[idx] = h;
    g_wfl[idx] = l;
}

// ---------------- tensor-core matmul kernel (mma.sync bf16, 3-term split) --
// TAPS in {3,5,7}: conv branch -> g_fused at channel offset c0.
// TAPS==0: 1x1 fusion GEMM with attention gate -> out[b][tok][e].
// CTA: 128 tokens x 128 out-channels; 8 warps (4M x 2N); K chunks of 64.
// A SMEM: [k][tok] rows 272B, loaded with ldmatrix.trans. W SMEM: [n][k] rows 144B.
template<int TAPS>
__global__ __launch_bounds__(256, 2) void mm_kernel(const float* __restrict__ bias,
                                                    float* __restrict__ out, int c0) {
    extern __shared__ char smem[];
    uint16_t* Ah = (uint16_t*)(smem + OFF_AH);
    uint16_t* Al = (uint16_t*)(smem + OFF_AL);
    uint16_t* Wh = (uint16_t*)(smem + OFF_WH);
    uint16_t* Wl = (uint16_t*)(smem + OFF_WL);
    float* s_attn = (float*)(smem + OFF_ATTN);

    const int tid = threadIdx.x;
    const int b   = blockIdx.y;
    const int tileTok = blockIdx.x * 128;
    const int nb = (TAPS == 0) ? blockIdx.z : 0;

    if (TAPS == 0)
        for (int i = tid; i < EE; i += 256) s_attn[i] = g_attn[b * EE + i];

    const int lane = tid & 31, wid = tid >> 5;
    const int wm = wid & 3, wn = wid >> 2;
    const int oL = tid & 127, hf = tid >> 7;

    float acc[2][8][4];
    #pragma unroll
    for (int mi = 0; mi < 2; ++mi)
        #pragma unroll
        for (int ni = 0; ni < 8; ++ni)
            #pragma unroll
            for (int q = 0; q < 4; ++q) acc[mi][ni][q] = 0.f;

    const uint32_t sAh = smem_u32(Ah), sAl = smem_u32(Al);
    const uint32_t sWh = smem_u32(Wh), sWl = smem_u32(Wl);

    const int NT  = (TAPS == 0) ? 1 : TAPS * TAPS;
    const int NCC = (TAPS == 0) ? 6 : 2;   // 64-wide K chunks per tap
    const uint16_t* gwh = (TAPS == 3) ? g_w3h : (TAPS == 5) ? g_w5h
                         : (TAPS == 7) ? g_w7h : g_wfh;
    const uint16_t* gwl = (TAPS == 3) ? g_w3l : (TAPS == 5) ? g_w5l
                         : (TAPS == 7) ? g_w7l : g_wfl;

    // ldmatrix addresses
    // A (trans, rows=k): lanes 0-7 k0-7/m0, 8-15 k0-7/m8, 16-23 k8-15/m0, 24-31 k8-15/m8
    const uint32_t aRow0 = (lane & 7) + ((lane >> 4) << 3);
    const uint32_t aCol0 = wm * 32 + ((lane >> 3) & 1) * 8;
    // W (non-trans, rows=n): lanes 0-7 n0-7@k0, 8-15 n0-7@k8, 16-23 n8-15@k0, 24-31 n8-15@k8
    const uint32_t wRow0 = wn * 64 + (lane & 7) + ((lane >> 4) << 3);
    const uint32_t wKoff = ((lane >> 3) & 1) << 3;

    // staging maps
    const int r0c = tid >> 6;       // conv: ci row base (stride 4)
    const int cA  = tid & 63;       // conv: u32 col (toks 2cA, 2cA+1)
    const int pyB = tileTok >> 6;

    for (int tap = 0; tap < NT; ++tap) {
        uint32_t mask = 0xFFFFFFFFu;
        const uint16_t *ph = nullptr, *pl = nullptr;
        long long Bv = 0;
        if (TAPS > 0) {
            int dy = tap / TAPS - TAPS / 2, dx = tap % TAPS - TAPS / 2;
            int B  = tileTok + dy * 64 + dx;
            int s  = B & 1;
            Bv = B - s;
            ph = (s ? g_xh1 : g_xh0) + GUARD;
            pl = (s ? g_xl1 : g_xl0) + GUARD;
            bool rv0 = (unsigned)(pyB + dy) < 64u;
            bool rv1 = (unsigned)(pyB + 1 + dy) < 64u;
            int lo = dx > 0 ? 0 : -dx;
            int hi = dx > 0 ? 64 - dx : 64;
            int j0 = cA * 2, j1 = j0 + 1;
            bool v0 = ((j0 >> 6) ? rv1 : rv0) && ((j0 & 63) >= lo) && ((j0 & 63) < hi);
            bool v1 = ((j1 >> 6) ? rv1 : rv0) && ((j1 & 63) >= lo) && ((j1 & 63) < hi);
            mask = (v0 ? 0xFFFFu : 0u) | (v1 ? 0xFFFF0000u : 0u);
        }

        for (int cc = 0; cc < NCC; ++cc) {
            __syncthreads();   // previous chunk's compute done

            // ---- stage A: [64 k][128 tok], hi/lo planes ----
            if (TAPS > 0) {
                long long base = (long long)(b * CIN + cc * 64 + r0c) * HWN + Bv;
                #pragma unroll
                for (int it = 0; it < 16; ++it) {
                    uint32_t uh = __ldg((const uint32_t*)(ph + base) + cA) & mask;
                    uint32_t ul = __ldg((const uint32_t*)(pl + base) + cA) & mask;
                    int r = r0c + it * 4;
                    *(uint32_t*)((char*)Ah + r * AROW + cA * 4) = uh;
                    *(uint32_t*)((char*)Al + r * AROW + cA * 4) = ul;
                    base += 4LL * HWN;
                }
            } else {
                const int rB = tid >> 5, c4 = tid & 31;
                const int cb = cc * 64;
                #pragma unroll
                for (int it = 0; it < 8; ++it) {
                    int r = rB + it * 8;
                    float4 v = __ldg((const float4*)(g_fused +
                                    ((size_t)b * EE + cb + r) * HWN + tileTok) + c4);
                    float a = s_attn[cb + r];
                    uint16_t h0, l0, h1, l1, h2, l2, h3, l3;
                    bf_split(v.x * a, h0, l0);
                    bf_split(v.y * a, h1, l1);
                    bf_split(v.z * a, h2, l2);
                    bf_split(v.w * a, h3, l3);
                    uint2 hh = make_uint2((uint32_t)h0 | ((uint32_t)h1 << 16),
                                          (uint32_t)h2 | ((uint32_t)h3 << 16));
                    uint2 ll = make_uint2((uint32_t)l0 | ((uint32_t)l1 << 16),
                                          (uint32_t)l2 | ((uint32_t)l3 << 16));
                    *(uint2*)((char*)Ah + r * AROW + c4 * 8) = hh;
                    *(uint2*)((char*)Al + r * AROW + c4 * 8) = ll;
                }
            }

            // ---- stage W: [128 n][64 k], uint4 copies, conflict-free ----
            {
                size_t roff = (TAPS == 0)
                    ? ((size_t)(nb * 128 + oL) * EE + cc * 64 + hf * 32)
                    : ((size_t)(tap * 128 + oL) * 128 + cc * 64 + hf * 32);
                #pragma unroll
                for (int jj = 0; jj < 4; ++jj) {
                    uint4 vh = __ldg((const uint4*)(gwh + roff + jj * 8));
                    uint4 vl = __ldg((const uint4*)(gwl + roff + jj * 8));
                    *(uint4*)((char*)Wh + oL * WROW + hf * 64 + jj * 16) = vh;
                    *(uint4*)((char*)Wl + oL * WROW + hf * 64 + jj * 16) = vl;
                }
            }
            __syncthreads();

            // ---- compute: 4 k16 steps, 3-term bf16 split ----
            #pragma unroll
            for (int k16 = 0; k16 < 4; ++k16) {
                const uint32_t kb = k16 * 16;
                uint32_t ahf[2][4], alf[2][4];
                #pragma unroll
                for (int mi = 0; mi < 2; ++mi) {
                    uint32_t ao = (kb + aRow0) * AROW + (aCol0 + mi * 16) * 2;
                    LDSM_X4T(ahf[mi][0], ahf[mi][1], ahf[mi][2], ahf[mi][3], sAh + ao);
                    LDSM_X4T(alf[mi][0], alf[mi][1], alf[mi][2], alf[mi][3], sAl + ao);
                }
                #pragma unroll
                for (int nh = 0; nh < 4; ++nh) {
                    uint32_t wo = (wRow0 + nh * 16) * WROW + (kb + wKoff) * 2;
                    uint32_t whf[4], wlf[4];
                    LDSM_X4(whf[0], whf[1], whf[2], whf[3], sWh + wo);
                    LDSM_X4(wlf[0], wlf[1], wlf[2], wlf[3], sWl + wo);
                    #pragma unroll
                    for (int mi = 0; mi < 2; ++mi) {
                        mma_bf16(acc[mi][nh * 2],     ahf[mi], whf[0], whf[1]);
                        mma_bf16(acc[mi][nh * 2 + 1], ahf[mi], whf[2], whf[3]);
                        mma_bf16(acc[mi][nh * 2],     alf[mi], whf[0], whf[1]);
                        mma_bf16(acc[mi][nh * 2 + 1], alf[mi], whf[2], whf[3]);
                        mma_bf16(acc[mi][nh * 2],     ahf[mi], wlf[0], wlf[1]);
                        mma_bf16(acc[mi][nh * 2 + 1], ahf[mi], wlf[2], wlf[3]);
                    }
                }
            }
        }
    }

    // ---- epilogue ----
    const int r0 = wm * 32 + (lane >> 2);
    if (TAPS > 0) {
        #pragma unroll
        for (int ni = 0; ni < 8; ++ni) {
            int ch = wn * 64 + ni * 8 + (lane & 3) * 2;
            float bv0 = __ldg(bias + ch), bv1 = __ldg(bias + ch + 1);
            float* d0 = g_fused + ((size_t)b * EE + c0 + ch) * HWN + tileTok;
            float* d1 = d0 + HWN;
            #pragma unroll
            for (int mi = 0; mi < 2; ++mi) {
                int m = r0 + mi * 16;
                d0[m]     = acc[mi][ni][0] + bv0;
                d1[m]     = acc[mi][ni][1] + bv1;
                d0[m + 8] = acc[mi][ni][2] + bv0;
                d1[m + 8] = acc[mi][ni][3] + bv1;
            }
        }
    } else {
        #pragma unroll
        for (int ni = 0; ni < 8; ++ni) {
            int chl = wn * 64 + ni * 8 + (lane & 3) * 2;
            int e = nb * 128 + chl;
            float bv0 = __ldg(bias + e), bv1 = __ldg(bias + e + 1);
            #pragma unroll
            for (int mi = 0; mi < 2; ++mi) {
                int m = r0 + mi * 16;
                float* da = out + ((size_t)b * HWN + tileTok + m) * EE + e;
                float* db = out + ((size_t)b * HWN + tileTok + m + 8) * EE + e;
                *(float2*)da = make_float2(acc[mi][ni][0] + bv0, acc[mi][ni][1] + bv1);
                *(float2*)db = make_float2(acc[mi][ni][2] + bv0, acc[mi][ni][3] + bv1);
            }
        }
    }
}

// ---------------- pool / attention / layernorm (unchanged, passing) ------
__global__ void pool_kernel() {
    int row = blockIdx.x;
    const float* p = g_fused + (size_t)row * HWN;
    int tid = threadIdx.x;
    float s = 0.f, m = -INFINITY;
    for (int i = tid; i < HWN; i += 256) { float v = p[i]; s += v; m = fmaxf(m, v); }
    __shared__ float ss[256], sm[256];
    ss[tid] = s; sm[tid] = m;
    __syncthreads();
    for (int st = 128; st > 0; st >>= 1) {
        if (tid < st) { ss[tid] += ss[tid + st]; sm[tid] = fmaxf(sm[tid], sm[tid + st]); }
        __syncthreads();
    }
    if (tid == 0) { g_avg[row] = ss[0] * (1.f / HWN); g_max[row] = sm[0]; }
}

__global__ void attn_kernel(const float* __restrict__ cw1, const float* __restrict__ cw2) {
    __shared__ float h1[24], h2[24];
    int b = blockIdx.x;
    int tid = threadIdx.x;
    if (tid < 24) {
        float s = 0.f;
        const float* w = cw1 + tid * EE;
        const float* v = g_avg + b * EE;
        #pragma unroll 4
        for (int c = 0; c < EE; ++c) s += v[c] * w[c];
        h1[tid] = fmaxf(s, 0.f);
    } else if (tid < 48) {
        int j = tid - 24;
        float s = 0.f;
        const float* w = cw1 + j * EE;
        const float* v = g_max + b * EE;
        #pragma unroll 4
        for (int c = 0; c < EE; ++c) s += v[c] * w[c];
        h2[j] = fmaxf(s, 0.f);
    }
    __syncthreads();
    float s = 0.f;
    const float* w = cw2 + tid * 24;
    #pragma unroll
    for (int j = 0; j < 24; ++j) s += (h1[j] + h2[j]) * w[j];
    g_attn[b * EE + tid] = 1.f / (1.f + expf(-s));
}

__global__ void ln_kernel(float* __restrict__ out, const float* __restrict__ g,
                          const float* __restrict__ beta) {
    int tokrow = blockIdx.x;
    float* p = out + (size_t)tokrow * EE;
    int tid = threadIdx.x;
    float v0 = p[tid], v1 = p[tid + 128], v2 = p[tid + 256];
    float s = v0 + v1 + v2;
    float q = v0 * v0 + v1 * v1 + v2 * v2;
    #pragma unroll
    for (int off = 16; off > 0; off >>= 1) {
        s += __shfl_down_sync(0xffffffffu, s, off);
        q += __shfl_down_sync(0xffffffffu, q, off);
    }
    __shared__ float rs[4], rq[4];
    __shared__ float smean, srstd;
    int wid = tid >> 5, lane = tid & 31;
    if (lane == 0) { rs[wid] = s; rq[wid] = q; }
    __syncthreads();
    if (tid == 0) {
        float ts = rs[0] + rs[1] + rs[2] + rs[3];
        float tq = rq[0] + rq[1] + rq[2] + rq[3];
        float mean = ts * (1.f / EE);
        float var  = tq * (1.f / EE) - mean * mean;
        smean = mean;
        srstd = rsqrtf(var + 1e-5f);
    }
    __syncthreads();
    float mean = smean, rstd = srstd;
    p[tid]       = (v0 - mean) * rstd * g[tid]       + beta[tid];
    p[tid + 128] = (v1 - mean) * rstd * g[tid + 128] + beta[tid + 128];
    p[tid + 256] = (v2 - mean) * rstd * g[tid + 256] + beta[tid + 256];
}

// ---------------- launch ---------------------------------------------------
extern "C" void kernel_launch(void* const* d_in, const int* in_sizes, int n_in,
                              void* d_out, int out_size) {
    const float* x   = (const float*)d_in[0];
    const float* w3  = (const float*)d_in[1];
    const float* b3  = (const float*)d_in[2];
    const float* w5  = (const float*)d_in[3];
    const float* b5  = (const float*)d_in[4];
    const float* w7  = (const float*)d_in[5];
    const float* b7  = (const float*)d_in[6];
    const float* cw1 = (const float*)d_in[7];
    const float* cw2 = (const float*)d_in[8];
    const float* fw  = (const float*)d_in[9];
    const float* fb  = (const float*)d_in[10];
    const float* lng = (const float*)d_in[11];
    const float* lnb = (const float*)d_in[12];
    float* out = (float*)d_out;

    cudaFuncSetAttribute(mm_kernel<3>, cudaFuncAttributeMaxDynamicSharedMemorySize, SMEM_SZ);
    cudaFuncSetAttribute(mm_kernel<5>, cudaFuncAttributeMaxDynamicSharedMemorySize, SMEM_SZ);
    cudaFuncSetAttribute(mm_kernel<7>, cudaFuncAttributeMaxDynamicSharedMemorySize, SMEM_SZ);
    cudaFuncSetAttribute(mm_kernel<0>, cudaFuncAttributeMaxDynamicSharedMemorySize, SMEM_SZ);

    prep_x<<<(int)((NX + 255) / 256), 256>>>(x);
    prep_wc<3><<<(9  * 16384 + 255) / 256, 256>>>(w3);
    prep_wc<5><<<(25 * 16384 + 255) / 256, 256>>>(w5);
    prep_wc<7><<<(49 * 16384 + 255) / 256, 256>>>(w7);
    prep_wf<<<(EE * EE + 255) / 256, 256>>>(fw);

    dim3 cgrid(HWN / 128, BATCH);
    mm_kernel<3><<<cgrid, 256, SMEM_SZ>>>(b3, nullptr, 0);
    mm_kernel<5><<<cgrid, 256, SMEM_SZ>>>(b5, nullptr, EB);
    mm_kernel<7><<<cgrid, 256, SMEM_SZ>>>(b7, nullptr, 2 * EB);

    pool_kernel<<<BATCH * EE, 256>>>();
    attn_kernel<<<BATCH, EE>>>(cw1, cw2);

    dim3 ggrid(HWN / 128, BATCH, 3);
    mm_kernel<0><<<ggrid, 256, SMEM_SZ>>>(fb, out, 0);

    ln_kernel<<<BATCH * HWN, 128>>>(out, lng, lnb);
}